// round 15
// baseline (speedup 1.0000x reference)
#include <cuda_runtime.h>
#include <cuda_fp16.h>
#include <math_constants.h>
#include <cstdint>

#define D_MODEL   1024
#define NUM_HEADS 16
#define D_HEAD    64
#define PATCH     128
#define BATCH     4
#define SEQ       8192
#define M_TOTAL   (BATCH * SEQ)          // 32768 rows
#define NBLK      (M_TOTAL / PATCH)      // 256 patch blocks

// ---------------------------------------------------------------------------
// Scratch (static device globals — no runtime allocation)
// ---------------------------------------------------------------------------
__device__ __half g_x[(size_t)M_TOTAL * D_MODEL];
__device__ __half g_Q[(size_t)M_TOTAL * D_MODEL];
__device__ __half g_K[(size_t)M_TOTAL * D_MODEL];
__device__ __half g_V[(size_t)M_TOTAL * D_MODEL];
__device__ __half g_A[(size_t)M_TOTAL * D_MODEL];
// transposed weights, 4 planes: 0=Wq^T,1=Wk^T,2=Wv^T,3=Wo^T (row n, col k)
__device__ __half g_w[(size_t)4 * D_MODEL * D_MODEL];

// ---------------------------------------------------------------------------
// PTX helpers (base ISA only)
// ---------------------------------------------------------------------------
__device__ __forceinline__ uint32_t smem_u32(const void* p) {
    uint32_t a;
    asm("{ .reg .u64 t; cvta.to.shared.u64 t, %1; cvt.u32.u64 %0, t; }" : "=r"(a) : "l"(p));
    return a;
}
__device__ __forceinline__ void cp16(uint32_t dst, const void* src) {
    asm volatile("cp.async.cg.shared.global [%0], [%1], 16;" :: "r"(dst), "l"(src));
}
#define CP_COMMIT() asm volatile("cp.async.commit_group;" ::: "memory")
#define CP_WAIT2()  asm volatile("cp.async.wait_group 2;" ::: "memory")
#define CP_WAIT1()  asm volatile("cp.async.wait_group 1;" ::: "memory")
#define CP_WAIT0()  asm volatile("cp.async.wait_group 0;" ::: "memory")

#define LDSM4(r0, r1, r2, r3, addr) \
    asm volatile("ldmatrix.sync.aligned.m8n8.x4.shared.b16 {%0,%1,%2,%3}, [%4];" \
        : "=r"(r0), "=r"(r1), "=r"(r2), "=r"(r3) : "r"(addr))

#define LDSM4T(r0, r1, r2, r3, addr) \
    asm volatile("ldmatrix.sync.aligned.m8n8.x4.trans.shared.b16 {%0,%1,%2,%3}, [%4];" \
        : "=r"(r0), "=r"(r1), "=r"(r2), "=r"(r3) : "r"(addr))

// fp16 inputs, fp32 accumulator (half-rate on this part's legacy path)
#define MMA_F32(c, a, b0, b1) \
    asm volatile("mma.sync.aligned.m16n8k16.row.col.f32.f16.f16.f32 " \
        "{%0,%1,%2,%3}, {%4,%5,%6,%7}, {%8,%9}, {%0,%1,%2,%3};" \
        : "+f"((c)[0]), "+f"((c)[1]), "+f"((c)[2]), "+f"((c)[3]) \
        : "r"((a)[0]), "r"((a)[1]), "r"((a)[2]), "r"((a)[3]), "r"(b0), "r"(b1))

// fp16 inputs, fp16 accumulator, C = 0 (rate probe: possibly full-rate)
#define MMA_F16Z(d0, d1, a, b0, b1) \
    asm volatile("mma.sync.aligned.m16n8k16.row.col.f16.f16.f16.f16 " \
        "{%0,%1}, {%2,%3,%4,%5}, {%6,%7}, {%8,%8};" \
        : "=r"(d0), "=r"(d1) \
        : "r"((a)[0]), "r"((a)[1]), "r"((a)[2]), "r"((a)[3]), "r"(b0), "r"(b1), "r"(0u))

__device__ __forceinline__ uint32_t packh2(float x, float y) {
    __half2 h = __floats2half2_rn(x, y);
    return *reinterpret_cast<uint32_t*>(&h);
}
// single-MUFU exp2 (inputs <= 0 here; approx err ~2^-22)
__device__ __forceinline__ float ex2f(float x) {
    float r;
    asm("ex2.approx.f32 %0, %1;" : "=f"(r) : "f"(x));
    return r;
}

// ---------------------------------------------------------------------------
// Fused prep: z<4 -> transpose+convert weight plane z; z==4 -> convert x.
// grid (32,32,5), block (32,8).
// ---------------------------------------------------------------------------
__global__ void prep_kernel(const float* __restrict__ W0, const float* __restrict__ W1,
                            const float* __restrict__ W2, const float* __restrict__ W3,
                            const float4* __restrict__ x, uint32_t* __restrict__ xh)
{
    if (blockIdx.z == 4) {
        const int tid = threadIdx.y * 32 + threadIdx.x;
        const int bid = blockIdx.y * 32 + blockIdx.x;
        const int n4 = M_TOTAL * D_MODEL / 4;
        for (int i = bid * 256 + tid; i < n4; i += 1024 * 256) {
            float4 v = x[i];
            xh[i * 2 + 0] = packh2(v.x, v.y);
            xh[i * 2 + 1] = packh2(v.z, v.w);
        }
        return;
    }
    __shared__ float t[32][33];
    const float* W = blockIdx.z == 0 ? W0 : blockIdx.z == 1 ? W1 : blockIdx.z == 2 ? W2 : W3;
    __half* T = g_w + (size_t)blockIdx.z * D_MODEL * D_MODEL;
    int bx = blockIdx.x * 32, by = blockIdx.y * 32;
    int xx = threadIdx.x, yy = threadIdx.y;
    #pragma unroll
    for (int d = 0; d < 32; d += 8)
        t[yy + d][xx] = W[(size_t)(by + yy + d) * D_MODEL + bx + xx];
    __syncthreads();
    #pragma unroll
    for (int d = 0; d < 32; d += 8)
        T[(size_t)(bx + yy + d) * D_MODEL + by + xx] = __float2half_rn(t[xx][yy + d]);
}

// ---------------------------------------------------------------------------
// fp16 GEMM: out_plane = A @ Bplane^T + bias_plane.
// CTA 128x128, BK=32, 4-stage cp.async pipeline, 1 chunk per sync.
// 8 warps, warp tile 64x32; 2 CTAs/SM.
// F16ACC: per-MMA fp16 accumulate (C=0) flushed to fp32 regs — rate probe.
// plane = blockIdx.x>>3 selects bias/output; col0 = (blockIdx.x&7)*128.
// ---------------------------------------------------------------------------
#define A_PLANE   10240
#define STAGE_B   20480
#define N_STAGES  4
#define GEMM_SMEM (N_STAGES * STAGE_B)
#define KCHUNKS   32

template<bool F32OUT, bool F16ACC>
__global__ __launch_bounds__(256, 2)
void gemm_f16(const __half* __restrict__ A, const __half* __restrict__ B,
              const float* __restrict__ b0, const float* __restrict__ b1,
              const float* __restrict__ b2,
              float* __restrict__ C,
              __half* __restrict__ o0, __half* __restrict__ o1,
              __half* __restrict__ o2)
{
    extern __shared__ char smem_raw[];
    const uint32_t sbase = smem_u32(smem_raw);

    const int tid    = threadIdx.x;
    const int wid    = tid >> 5;
    const int lane   = tid & 31;
    const int warp_m = (wid >> 2) * 64;    // 0 or 64
    const int warp_n = (wid & 3) * 32;     // 0,32,64,96
    const size_t m0  = (size_t)blockIdx.y * 128;
    const size_t n0  = (size_t)blockIdx.x * 128;     // row in (possibly multi-plane) B
    const int plane  = blockIdx.x >> 3;
    const int col0   = (blockIdx.x & 7) * 128;       // column within output plane

    const float* bias = plane == 0 ? b0 : plane == 1 ? b1 : b2;
    __half* Ch        = plane == 0 ? o0 : plane == 1 ? o1 : o2;

    const char* sA = (const char*)(A + m0 * D_MODEL);
    const char* sB = (const char*)(B + n0 * D_MODEL);

    auto fill = [&](int stage, int kc) {
        const uint32_t st = sbase + stage * STAGE_B;
        const size_t ko = (size_t)kc * 64;
        #pragma unroll
        for (int i = 0; i < 2; i++) {
            int c = tid + i * 256, row = c >> 2, col = c & 3;
            cp16(st + row * 80 + col * 16, sA + (size_t)row * 2048 + ko + col * 16);
        }
        #pragma unroll
        for (int i = 0; i < 2; i++) {
            int c = tid + i * 256, row = c >> 2, col = c & 3;
            cp16(st + A_PLANE + row * 80 + col * 16, sB + (size_t)row * 2048 + ko + col * 16);
        }
        CP_COMMIT();
    };

    float acc[4][4][4];
    #pragma unroll
    for (int i = 0; i < 4; i++)
        #pragma unroll
        for (int j = 0; j < 4; j++)
            #pragma unroll
            for (int q = 0; q < 4; q++) acc[i][j][q] = 0.f;

    // prologue: chunks 0..2 into stages 0..2 (3 groups)
    fill(0, 0); fill(1, 1); fill(2, 2);

    const int lr = lane & 7, g = lane >> 3;
    const uint32_t a_loff = (uint32_t)((lr + (g & 1) * 8) * 80 + (g >> 1) * 16);
    const uint32_t b_loff = (uint32_t)((lr + (g >> 1) * 8) * 80 + (g & 1) * 16);

    #pragma unroll 1
    for (int j = 0; j < KCHUNKS; j++) {
        CP_WAIT2();              // chunks <= j resident (j+1, j+2 in flight)
        __syncthreads();         // all warps done reading stage (j-1)%4 (refilled below)
        if (j + 3 < KCHUNKS) fill((j + 3) % N_STAGES, j + 3);
        else CP_COMMIT();        // keep group counting uniform

        const uint32_t st = sbase + (j % N_STAGES) * STAGE_B;
        const uint32_t aP = st +           warp_m * 80 + a_loff;
        const uint32_t bP = st + A_PLANE + warp_n * 80 + b_loff;
        #pragma unroll
        for (int ks = 0; ks < 2; ks++) {
            const uint32_t ko = ks * 32;
            uint32_t a_r[4][4], b_r[8];
            #pragma unroll
            for (int mt = 0; mt < 4; mt++)
                LDSM4(a_r[mt][0], a_r[mt][1], a_r[mt][2], a_r[mt][3],
                      aP + mt * (16 * 80) + ko);
            #pragma unroll
            for (int p = 0; p < 2; p++)
                LDSM4(b_r[p*4+0], b_r[p*4+1], b_r[p*4+2], b_r[p*4+3],
                      bP + p * (16 * 80) + ko);
            #pragma unroll
            for (int mt = 0; mt < 4; mt++)
                #pragma unroll
                for (int nt = 0; nt < 4; nt++) {
                    if constexpr (F16ACC) {
                        uint32_t d0, d1;
                        MMA_F16Z(d0, d1, a_r[mt], b_r[nt*2], b_r[nt*2+1]);
                        float2 f0 = __half22float2(*reinterpret_cast<__half2*>(&d0));
                        float2 f1 = __half22float2(*reinterpret_cast<__half2*>(&d1));
                        acc[mt][nt][0] += f0.x; acc[mt][nt][1] += f0.y;
                        acc[mt][nt][2] += f1.x; acc[mt][nt][3] += f1.y;
                    } else {
                        MMA_F32(acc[mt][nt], a_r[mt], b_r[nt*2], b_r[nt*2+1]);
                    }
                }
        }
    }

    #pragma unroll
    for (int mt = 0; mt < 4; mt++) {
        #pragma unroll
        for (int nt = 0; nt < 4; nt++) {
            int row0 = (int)m0 + warp_m + mt * 16 + (lane >> 2);
            int colg = col0 + warp_n + nt * 8 + (lane & 3) * 2;
            float2 bv = *reinterpret_cast<const float2*>(bias + colg);
            float o00 = acc[mt][nt][0] + bv.x, o01 = acc[mt][nt][1] + bv.y;
            float o10 = acc[mt][nt][2] + bv.x, o11 = acc[mt][nt][3] + bv.y;
            size_t off0 = (size_t)row0 * D_MODEL + colg;
            size_t off1 = off0 + 8 * D_MODEL;
            if constexpr (F32OUT) {
                float2 a{o00, o01}, b{o10, o11};
                *reinterpret_cast<float2*>(C + off0) = a;
                *reinterpret_cast<float2*>(C + off1) = b;
            } else {
                *reinterpret_cast<uint32_t*>(Ch + off0) = packh2(o00, o01);
                *reinterpret_cast<uint32_t*>(Ch + off1) = packh2(o10, o11);
            }
        }
    }
}

// ---------------------------------------------------------------------------
// Tensor-core patch attention (fp16, fragment softmax, MUFU ex2, trans-LDSM V).
// V load in a second cp.async group — its latency hides behind S + softmax.
// grid = (NUM_HEADS, NBLK), 256 threads (8 warps; warp w owns rows 16w..16w+15).
// smem: Q,K,V each [128][72] fp16 (144B stride) = 55296 B.
// ---------------------------------------------------------------------------
#define QK_STRIDE_B 144          // 72 fp16
#define OFF_Q 0
#define OFF_K 18432
#define OFF_V 36864
#define ATTN_SMEM 55296

__global__ __launch_bounds__(256, 2)
void attn_mma_kernel()
{
    extern __shared__ char smc[];
    const uint32_t sb = smem_u32(smc);

    const int h   = blockIdx.x;
    const int pb  = blockIdx.y;
    const int tid = threadIdx.x;
    const int wid = tid >> 5;
    const int lane = tid & 31;
    const size_t base = (size_t)pb * 128 * D_MODEL + (size_t)h * D_HEAD;

    // group 0: Q + K;  group 1: V (latency hidden behind S + softmax)
    {
        const char* gq = (const char*)(g_Q + base);
        const char* gk = (const char*)(g_K + base);
        const char* gv = (const char*)(g_V + base);
        #pragma unroll
        for (int i = 0; i < 4; i++) {
            int idx = tid + i * 256;
            int row = idx >> 3, ch = idx & 7;
            uint32_t so = row * QK_STRIDE_B + ch * 16;
            size_t  go = (size_t)row * 2048 + ch * 16;
            cp16(sb + OFF_Q + so, gq + go);
            cp16(sb + OFF_K + so, gk + go);
        }
        CP_COMMIT();
        #pragma unroll
        for (int i = 0; i < 4; i++) {
            int idx = tid + i * 256;
            int row = idx >> 3, ch = idx & 7;
            cp16(sb + OFF_V + row * QK_STRIDE_B + ch * 16,
                 gv + (size_t)row * 2048 + ch * 16);
        }
        CP_COMMIT();
    }
    CP_WAIT1();          // Q, K resident (V still in flight)
    __syncthreads();

    const int lr = lane & 7, g = lane >> 3;
    const uint32_t a_off = (uint32_t)((lr + (g & 1) * 8) * QK_STRIDE_B + (g >> 1) * 16);
    const uint32_t b_off = (uint32_t)((lr + (g >> 1) * 8) * QK_STRIDE_B + (g & 1) * 16);
    const uint32_t v_off = (uint32_t)((lane & 15) * QK_STRIDE_B + (lane >> 4) * 16);

    // ---- S = Q K^T ----
    float cf[16][4];
    #pragma unroll
    for (int i = 0; i < 16; i++)
        #pragma unroll
        for (int q = 0; q < 4; q++) cf[i][q] = 0.f;

    const uint32_t q0 = sb + OFF_Q + wid * (16 * QK_STRIDE_B) + a_off;

    #pragma unroll
    for (int ks = 0; ks < 4; ks++) {
        const uint32_t ko = ks * 32;
        uint32_t aq[4];
        LDSM4(aq[0], aq[1], aq[2], aq[3], q0 + ko);
        #pragma unroll
        for (int p = 0; p < 8; p++) {
            uint32_t kh[4];
            LDSM4(kh[0], kh[1], kh[2], kh[3], sb + OFF_K + p * (16 * QK_STRIDE_B) + b_off + ko);
            MMA_F32(cf[2*p],   aq, kh[0], kh[1]);
            MMA_F32(cf[2*p+1], aq, kh[2], kh[3]);
        }
    }

    // ---- fragment softmax (MUFU exp2) ----
    float mx0 = -CUDART_INF_F, mx1 = -CUDART_INF_F;
    #pragma unroll
    for (int nt = 0; nt < 16; nt++) {
        mx0 = fmaxf(mx0, fmaxf(cf[nt][0], cf[nt][1]));
        mx1 = fmaxf(mx1, fmaxf(cf[nt][2], cf[nt][3]));
    }
    mx0 = fmaxf(mx0, __shfl_xor_sync(0xffffffffu, mx0, 1));
    mx0 = fmaxf(mx0, __shfl_xor_sync(0xffffffffu, mx0, 2));
    mx1 = fmaxf(mx1, __shfl_xor_sync(0xffffffffu, mx1, 1));
    mx1 = fmaxf(mx1, __shfl_xor_sync(0xffffffffu, mx1, 2));

    const float CS = 0.125f * 1.4426950408889634f;   // log2(e)/sqrt(64)
    float l0 = 0.f, l1 = 0.f;
    #pragma unroll
    for (int nt = 0; nt < 16; nt++) {
        float p0 = ex2f((cf[nt][0] - mx0) * CS);
        float p1 = ex2f((cf[nt][1] - mx0) * CS);
        float p2 = ex2f((cf[nt][2] - mx1) * CS);
        float p3 = ex2f((cf[nt][3] - mx1) * CS);
        cf[nt][0] = p0; cf[nt][1] = p1; cf[nt][2] = p2; cf[nt][3] = p3;
        l0 += p0 + p1; l1 += p2 + p3;
    }
    l0 += __shfl_xor_sync(0xffffffffu, l0, 1);
    l0 += __shfl_xor_sync(0xffffffffu, l0, 2);
    l1 += __shfl_xor_sync(0xffffffffu, l1, 1);
    l1 += __shfl_xor_sync(0xffffffffu, l1, 2);
    const float inv0 = 1.f / l0, inv1 = 1.f / l1;

    // now V must be resident
    CP_WAIT0();
    __syncthreads();

    // ---- O = P V (B-frags via ldmatrix.trans from row-major V) ----
    float of[8][4];
    #pragma unroll
    for (int i = 0; i < 8; i++)
        #pragma unroll
        for (int q = 0; q < 4; q++) of[i][q] = 0.f;

    #pragma unroll
    for (int kt = 0; kt < 8; kt++) {
        uint32_t ah[4];
        ah[0] = packh2(cf[2*kt][0],   cf[2*kt][1]);
        ah[1] = packh2(cf[2*kt][2],   cf[2*kt][3]);
        ah[2] = packh2(cf[2*kt+1][0], cf[2*kt+1][1]);
        ah[3] = packh2(cf[2*kt+1][2], cf[2*kt+1][3]);
        const uint32_t vrow = sb + OFF_V + kt * (16 * QK_STRIDE_B) + v_off;
        #pragma unroll
        for (int np = 0; np < 4; np++) {
            uint32_t vh[4];
            LDSM4T(vh[0], vh[1], vh[2], vh[3], vrow + np * 32);
            MMA_F32(of[2*np],   ah, vh[0], vh[1]);
            MMA_F32(of[2*np+1], ah, vh[2], vh[3]);
        }
    }

    // ---- write A = softmax(S)V as fp16 ----
    const int row  = pb * 128 + wid * 16 + (lane >> 2);
    const int colb = h * 64 + (lane & 3) * 2;
    #pragma unroll
    for (int nt = 0; nt < 8; nt++) {
        size_t off0 = (size_t)row * D_MODEL + colb + nt * 8;
        size_t off1 = off0 + 8 * D_MODEL;
        *reinterpret_cast<uint32_t*>(g_A + off0) = packh2(of[nt][0] * inv0, of[nt][1] * inv0);
        *reinterpret_cast<uint32_t*>(g_A + off1) = packh2(of[nt][2] * inv1, of[nt][3] * inv1);
    }
}

// ---------------------------------------------------------------------------
extern "C" void kernel_launch(void* const* d_in, const int* in_sizes, int n_in,
                              void* d_out, int out_size)
{
    const float* x  = (const float*)d_in[0];
    // d_in[1] = coords (unused by reference)
    const float* Wq = (const float*)d_in[2];
    const float* bq = (const float*)d_in[3];
    const float* Wk = (const float*)d_in[4];
    const float* bk = (const float*)d_in[5];
    const float* Wv = (const float*)d_in[6];
    const float* bv = (const float*)d_in[7];
    const float* Wo = (const float*)d_in[8];
    const float* bo = (const float*)d_in[9];
    float* out = (float*)d_out;

    __half *xh, *Qp, *Kp, *Vp, *Ap, *wp;
    cudaGetSymbolAddress((void**)&xh, g_x);
    cudaGetSymbolAddress((void**)&Qp, g_Q);
    cudaGetSymbolAddress((void**)&Kp, g_K);
    cudaGetSymbolAddress((void**)&Vp, g_V);
    cudaGetSymbolAddress((void**)&Ap, g_A);
    cudaGetSymbolAddress((void**)&wp, g_w);

    cudaFuncSetAttribute((const void*)gemm_f16<true, false>,
                         cudaFuncAttributeMaxDynamicSharedMemorySize, GEMM_SMEM);
    cudaFuncSetAttribute((const void*)gemm_f16<false, true>,
                         cudaFuncAttributeMaxDynamicSharedMemorySize, GEMM_SMEM);
    cudaFuncSetAttribute(attn_mma_kernel, cudaFuncAttributeMaxDynamicSharedMemorySize, ATTN_SMEM);

    // launch 1: fused prep — transpose/convert weights (z<4) + convert x (z=4)
    dim3 pgrid(32, 32, 5), pblk(32, 8);
    prep_kernel<<<pgrid, pblk>>>(Wq, Wk, Wv, Wo, (const float4*)x, (uint32_t*)xh);

    // launch 2: fused Q/K/V projection (planes 0-2 of g_w), fp16 out, F16ACC probe
    dim3 qkv_grid(24, M_TOTAL / 128);   // 6144 CTAs (128x128 tiles)
    gemm_f16<false, true><<<qkv_grid, 256, GEMM_SMEM>>>(xh, wp, bq, bk, bv,
                                                        nullptr, Qp, Kp, Vp);

    // launch 3: tensor-core attention (fp16 A)
    dim3 agrid(NUM_HEADS, NBLK);
    attn_mma_kernel<<<agrid, 256, ATTN_SMEM>>>();

    // launch 4: output projection (plane 3 of g_w), fp32 out, f32-acc
    dim3 o_grid(8, M_TOTAL / 128);
    gemm_f16<true, false><<<o_grid, 256, GEMM_SMEM>>>(Ap, wp + (size_t)3 * D_MODEL * D_MODEL,
                                                      bo, bo, bo, out, nullptr, nullptr, nullptr);
}

// round 16
// speedup vs baseline: 1.2389x; 1.2389x over previous
#include <cuda_runtime.h>
#include <cuda_fp16.h>
#include <math_constants.h>
#include <cstdint>

#define D_MODEL   1024
#define NUM_HEADS 16
#define D_HEAD    64
#define PATCH     128
#define BATCH     4
#define SEQ       8192
#define M_TOTAL   (BATCH * SEQ)          // 32768 rows
#define NBLK      (M_TOTAL / PATCH)      // 256 patch blocks

// ---------------------------------------------------------------------------
// Scratch (static device globals — no runtime allocation)
// ---------------------------------------------------------------------------
__device__ __half g_x[(size_t)M_TOTAL * D_MODEL];
__device__ __half g_Q[(size_t)M_TOTAL * D_MODEL];
__device__ __half g_K[(size_t)M_TOTAL * D_MODEL];
__device__ __half g_V[(size_t)M_TOTAL * D_MODEL];
__device__ __half g_A[(size_t)M_TOTAL * D_MODEL];
// transposed weights, 4 planes: 0=Wq^T,1=Wk^T,2=Wv^T,3=Wo^T (row n, col k)
__device__ __half g_w[(size_t)4 * D_MODEL * D_MODEL];

// ---------------------------------------------------------------------------
// PTX helpers (base ISA only)
// ---------------------------------------------------------------------------
__device__ __forceinline__ uint32_t smem_u32(const void* p) {
    uint32_t a;
    asm("{ .reg .u64 t; cvta.to.shared.u64 t, %1; cvt.u32.u64 %0, t; }" : "=r"(a) : "l"(p));
    return a;
}
__device__ __forceinline__ void cp16(uint32_t dst, const void* src) {
    asm volatile("cp.async.cg.shared.global [%0], [%1], 16;" :: "r"(dst), "l"(src));
}
#define CP_COMMIT() asm volatile("cp.async.commit_group;" ::: "memory")
#define CP_WAIT2()  asm volatile("cp.async.wait_group 2;" ::: "memory")
#define CP_WAIT1()  asm volatile("cp.async.wait_group 1;" ::: "memory")
#define CP_WAIT0()  asm volatile("cp.async.wait_group 0;" ::: "memory")

#define LDSM4(r0, r1, r2, r3, addr) \
    asm volatile("ldmatrix.sync.aligned.m8n8.x4.shared.b16 {%0,%1,%2,%3}, [%4];" \
        : "=r"(r0), "=r"(r1), "=r"(r2), "=r"(r3) : "r"(addr))

#define LDSM4T(r0, r1, r2, r3, addr) \
    asm volatile("ldmatrix.sync.aligned.m8n8.x4.trans.shared.b16 {%0,%1,%2,%3}, [%4];" \
        : "=r"(r0), "=r"(r1), "=r"(r2), "=r"(r3) : "r"(addr))

#define MMA_F32(c, a, b0, b1) \
    asm volatile("mma.sync.aligned.m16n8k16.row.col.f32.f16.f16.f32 " \
        "{%0,%1,%2,%3}, {%4,%5,%6,%7}, {%8,%9}, {%0,%1,%2,%3};" \
        : "+f"((c)[0]), "+f"((c)[1]), "+f"((c)[2]), "+f"((c)[3]) \
        : "r"((a)[0]), "r"((a)[1]), "r"((a)[2]), "r"((a)[3]), "r"(b0), "r"(b1))

__device__ __forceinline__ uint32_t packh2(float x, float y) {
    __half2 h = __floats2half2_rn(x, y);
    return *reinterpret_cast<uint32_t*>(&h);
}
// single-MUFU exp2 (inputs <= 0 here; approx err ~2^-22)
__device__ __forceinline__ float ex2f(float x) {
    float r;
    asm("ex2.approx.f32 %0, %1;" : "=f"(r) : "f"(x));
    return r;
}

// ---------------------------------------------------------------------------
// Fused prep: z<4 -> transpose+convert weight plane z; z==4 -> convert x.
// grid (32,32,5), block (32,8).
// ---------------------------------------------------------------------------
__global__ void prep_kernel(const float* __restrict__ W0, const float* __restrict__ W1,
                            const float* __restrict__ W2, const float* __restrict__ W3,
                            const float4* __restrict__ x, uint32_t* __restrict__ xh)
{
    if (blockIdx.z == 4) {
        const int tid = threadIdx.y * 32 + threadIdx.x;
        const int bid = blockIdx.y * 32 + blockIdx.x;
        const int n4 = M_TOTAL * D_MODEL / 4;
        for (int i = bid * 256 + tid; i < n4; i += 1024 * 256) {
            float4 v = x[i];
            xh[i * 2 + 0] = packh2(v.x, v.y);
            xh[i * 2 + 1] = packh2(v.z, v.w);
        }
        return;
    }
    __shared__ float t[32][33];
    const float* W = blockIdx.z == 0 ? W0 : blockIdx.z == 1 ? W1 : blockIdx.z == 2 ? W2 : W3;
    __half* T = g_w + (size_t)blockIdx.z * D_MODEL * D_MODEL;
    int bx = blockIdx.x * 32, by = blockIdx.y * 32;
    int xx = threadIdx.x, yy = threadIdx.y;
    #pragma unroll
    for (int d = 0; d < 32; d += 8)
        t[yy + d][xx] = W[(size_t)(by + yy + d) * D_MODEL + bx + xx];
    __syncthreads();
    #pragma unroll
    for (int d = 0; d < 32; d += 8)
        T[(size_t)(bx + yy + d) * D_MODEL + by + xx] = __float2half_rn(t[xx][yy + d]);
}

// ---------------------------------------------------------------------------
// fp16 GEMM: out_plane = A @ Bplane^T + bias_plane.
// CTA 128x128, BK=32, 4-stage cp.async pipeline, 1 chunk per sync.
// Live set = 4 chunks (1 compute + 2 in-flight + 1 filling) = stage count.
// 8 warps, warp tile 64x32 (acc 64 regs) -> <=128 regs -> 2 CTAs/SM (16 warps).
// smem: 4 stages x 20480 B = 81920 B per CTA.
// plane = blockIdx.x>>3 selects bias/output; col0 = (blockIdx.x&7)*128.
// ---------------------------------------------------------------------------
#define A_PLANE   10240
#define STAGE_B   20480
#define N_STAGES  4
#define GEMM_SMEM (N_STAGES * STAGE_B)
#define KCHUNKS   32

template<bool F32OUT>
__global__ __launch_bounds__(256, 2)
void gemm_f16(const __half* __restrict__ A, const __half* __restrict__ B,
              const float* __restrict__ b0, const float* __restrict__ b1,
              const float* __restrict__ b2,
              float* __restrict__ C,
              __half* __restrict__ o0, __half* __restrict__ o1,
              __half* __restrict__ o2)
{
    extern __shared__ char smem_raw[];
    const uint32_t sbase = smem_u32(smem_raw);

    const int tid    = threadIdx.x;
    const int wid    = tid >> 5;
    const int lane   = tid & 31;
    const int warp_m = (wid >> 2) * 64;    // 0 or 64
    const int warp_n = (wid & 3) * 32;     // 0,32,64,96
    const size_t m0  = (size_t)blockIdx.y * 128;
    const size_t n0  = (size_t)blockIdx.x * 128;     // row in (possibly multi-plane) B
    const int plane  = blockIdx.x >> 3;
    const int col0   = (blockIdx.x & 7) * 128;       // column within output plane

    const float* bias = plane == 0 ? b0 : plane == 1 ? b1 : b2;
    __half* Ch        = plane == 0 ? o0 : plane == 1 ? o1 : o2;

    const char* sA = (const char*)(A + m0 * D_MODEL);
    const char* sB = (const char*)(B + n0 * D_MODEL);

    auto fill = [&](int stage, int kc) {
        const uint32_t st = sbase + stage * STAGE_B;
        const size_t ko = (size_t)kc * 64;
        #pragma unroll
        for (int i = 0; i < 2; i++) {
            int c = tid + i * 256, row = c >> 2, col = c & 3;
            cp16(st + row * 80 + col * 16, sA + (size_t)row * 2048 + ko + col * 16);
        }
        #pragma unroll
        for (int i = 0; i < 2; i++) {
            int c = tid + i * 256, row = c >> 2, col = c & 3;
            cp16(st + A_PLANE + row * 80 + col * 16, sB + (size_t)row * 2048 + ko + col * 16);
        }
        CP_COMMIT();
    };

    float acc[4][4][4];
    #pragma unroll
    for (int i = 0; i < 4; i++)
        #pragma unroll
        for (int j = 0; j < 4; j++)
            #pragma unroll
            for (int q = 0; q < 4; q++) acc[i][j][q] = 0.f;

    // prologue: chunks 0..2 into stages 0..2 (3 groups)
    fill(0, 0); fill(1, 1); fill(2, 2);

    const int lr = lane & 7, g = lane >> 3;
    const uint32_t a_loff = (uint32_t)((lr + (g & 1) * 8) * 80 + (g >> 1) * 16);
    const uint32_t b_loff = (uint32_t)((lr + (g >> 1) * 8) * 80 + (g & 1) * 16);

    #pragma unroll 1
    for (int j = 0; j < KCHUNKS; j++) {
        CP_WAIT2();              // chunks <= j resident (j+1, j+2 in flight)
        __syncthreads();         // all warps done reading stage (j-1)%4 (refilled below)
        if (j + 3 < KCHUNKS) fill((j + 3) % N_STAGES, j + 3);
        else CP_COMMIT();        // keep group counting uniform

        const uint32_t st = sbase + (j % N_STAGES) * STAGE_B;
        const uint32_t aP = st +           warp_m * 80 + a_loff;
        const uint32_t bP = st + A_PLANE + warp_n * 80 + b_loff;
        #pragma unroll
        for (int ks = 0; ks < 2; ks++) {
            const uint32_t ko = ks * 32;
            uint32_t a_r[4][4], b_r[8];
            #pragma unroll
            for (int mt = 0; mt < 4; mt++)
                LDSM4(a_r[mt][0], a_r[mt][1], a_r[mt][2], a_r[mt][3],
                      aP + mt * (16 * 80) + ko);
            #pragma unroll
            for (int p = 0; p < 2; p++)
                LDSM4(b_r[p*4+0], b_r[p*4+1], b_r[p*4+2], b_r[p*4+3],
                      bP + p * (16 * 80) + ko);
            #pragma unroll
            for (int mt = 0; mt < 4; mt++)
                #pragma unroll
                for (int nt = 0; nt < 4; nt++)
                    MMA_F32(acc[mt][nt], a_r[mt], b_r[nt*2], b_r[nt*2+1]);
        }
    }

    #pragma unroll
    for (int mt = 0; mt < 4; mt++) {
        #pragma unroll
        for (int nt = 0; nt < 4; nt++) {
            int row0 = (int)m0 + warp_m + mt * 16 + (lane >> 2);
            int colg = col0 + warp_n + nt * 8 + (lane & 3) * 2;
            float2 bv = *reinterpret_cast<const float2*>(bias + colg);
            float o00 = acc[mt][nt][0] + bv.x, o01 = acc[mt][nt][1] + bv.y;
            float o10 = acc[mt][nt][2] + bv.x, o11 = acc[mt][nt][3] + bv.y;
            size_t off0 = (size_t)row0 * D_MODEL + colg;
            size_t off1 = off0 + 8 * D_MODEL;
            if constexpr (F32OUT) {
                float2 a{o00, o01}, b{o10, o11};
                *reinterpret_cast<float2*>(C + off0) = a;
                *reinterpret_cast<float2*>(C + off1) = b;
            } else {
                *reinterpret_cast<uint32_t*>(Ch + off0) = packh2(o00, o01);
                *reinterpret_cast<uint32_t*>(Ch + off1) = packh2(o10, o11);
            }
        }
    }
}

// ---------------------------------------------------------------------------
// Tensor-core patch attention (fp16, fragment softmax, MUFU ex2, trans-LDSM V).
// 3-way cp.async split: group0 = Q + K[0:64], group1 = K[64:128], group2 = V.
// First half of S overlaps K's second half; V overlaps S + softmax.
// grid = (NUM_HEADS, NBLK), 256 threads (8 warps; warp w owns rows 16w..16w+15).
// smem: Q,K,V each [128][72] fp16 (144B stride) = 55296 B.
// ---------------------------------------------------------------------------
#define QK_STRIDE_B 144          // 72 fp16
#define OFF_Q 0
#define OFF_K 18432
#define OFF_V 36864
#define ATTN_SMEM 55296

__global__ __launch_bounds__(256, 2)
void attn_mma_kernel()
{
    extern __shared__ char smc[];
    const uint32_t sb = smem_u32(smc);

    const int h   = blockIdx.x;
    const int pb  = blockIdx.y;
    const int tid = threadIdx.x;
    const int wid = tid >> 5;
    const int lane = tid & 31;
    const size_t base = (size_t)pb * 128 * D_MODEL + (size_t)h * D_HEAD;

    // group 0: Q (all) + K rows 0..63;  group 1: K rows 64..127;  group 2: V
    {
        const char* gq = (const char*)(g_Q + base);
        const char* gk = (const char*)(g_K + base);
        const char* gv = (const char*)(g_V + base);
        #pragma unroll
        for (int i = 0; i < 4; i++) {
            int idx = tid + i * 256;
            int row = idx >> 3, ch = idx & 7;
            cp16(sb + OFF_Q + row * QK_STRIDE_B + ch * 16,
                 gq + (size_t)row * 2048 + ch * 16);
        }
        #pragma unroll
        for (int i = 0; i < 2; i++) {          // K rows 0..63 (idx 0..511)
            int idx = tid + i * 256;
            int row = idx >> 3, ch = idx & 7;
            cp16(sb + OFF_K + row * QK_STRIDE_B + ch * 16,
                 gk + (size_t)row * 2048 + ch * 16);
        }
        CP_COMMIT();
        #pragma unroll
        for (int i = 2; i < 4; i++) {          // K rows 64..127
            int idx = tid + i * 256;
            int row = idx >> 3, ch = idx & 7;
            cp16(sb + OFF_K + row * QK_STRIDE_B + ch * 16,
                 gk + (size_t)row * 2048 + ch * 16);
        }
        CP_COMMIT();
        #pragma unroll
        for (int i = 0; i < 4; i++) {
            int idx = tid + i * 256;
            int row = idx >> 3, ch = idx & 7;
            cp16(sb + OFF_V + row * QK_STRIDE_B + ch * 16,
                 gv + (size_t)row * 2048 + ch * 16);
        }
        CP_COMMIT();
    }
    CP_WAIT2();          // Q + K[0:64] resident (K tail, V in flight)
    __syncthreads();

    const int lr = lane & 7, g = lane >> 3;
    const uint32_t a_off = (uint32_t)((lr + (g & 1) * 8) * QK_STRIDE_B + (g >> 1) * 16);
    const uint32_t b_off = (uint32_t)((lr + (g >> 1) * 8) * QK_STRIDE_B + (g & 1) * 16);
    const uint32_t v_off = (uint32_t)((lane & 15) * QK_STRIDE_B + (lane >> 4) * 16);

    // ---- S = Q K^T ----
    float cf[16][4];
    #pragma unroll
    for (int i = 0; i < 16; i++)
        #pragma unroll
        for (int q = 0; q < 4; q++) cf[i][q] = 0.f;

    const uint32_t q0 = sb + OFF_Q + wid * (16 * QK_STRIDE_B) + a_off;

    // preload all Q fragments (one per ks)
    uint32_t aq[4][4];
    #pragma unroll
    for (int ks = 0; ks < 4; ks++)
        LDSM4(aq[ks][0], aq[ks][1], aq[ks][2], aq[ks][3], q0 + ks * 32);

    // first half: K blocks p = 0..3 (rows 0..63)
    #pragma unroll
    for (int p = 0; p < 4; p++) {
        #pragma unroll
        for (int ks = 0; ks < 4; ks++) {
            uint32_t kh[4];
            LDSM4(kh[0], kh[1], kh[2], kh[3],
                  sb + OFF_K + p * (16 * QK_STRIDE_B) + b_off + ks * 32);
            MMA_F32(cf[2*p],   aq[ks], kh[0], kh[1]);
            MMA_F32(cf[2*p+1], aq[ks], kh[2], kh[3]);
        }
    }

    CP_WAIT1();          // K tail resident (V in flight)
    __syncthreads();

    // second half: K blocks p = 4..7 (rows 64..127)
    #pragma unroll
    for (int p = 4; p < 8; p++) {
        #pragma unroll
        for (int ks = 0; ks < 4; ks++) {
            uint32_t kh[4];
            LDSM4(kh[0], kh[1], kh[2], kh[3],
                  sb + OFF_K + p * (16 * QK_STRIDE_B) + b_off + ks * 32);
            MMA_F32(cf[2*p],   aq[ks], kh[0], kh[1]);
            MMA_F32(cf[2*p+1], aq[ks], kh[2], kh[3]);
        }
    }

    // ---- fragment softmax (MUFU exp2) ----
    float mx0 = -CUDART_INF_F, mx1 = -CUDART_INF_F;
    #pragma unroll
    for (int nt = 0; nt < 16; nt++) {
        mx0 = fmaxf(mx0, fmaxf(cf[nt][0], cf[nt][1]));
        mx1 = fmaxf(mx1, fmaxf(cf[nt][2], cf[nt][3]));
    }
    mx0 = fmaxf(mx0, __shfl_xor_sync(0xffffffffu, mx0, 1));
    mx0 = fmaxf(mx0, __shfl_xor_sync(0xffffffffu, mx0, 2));
    mx1 = fmaxf(mx1, __shfl_xor_sync(0xffffffffu, mx1, 1));
    mx1 = fmaxf(mx1, __shfl_xor_sync(0xffffffffu, mx1, 2));

    const float CS = 0.125f * 1.4426950408889634f;   // log2(e)/sqrt(64)
    float l0 = 0.f, l1 = 0.f;
    #pragma unroll
    for (int nt = 0; nt < 16; nt++) {
        float p0 = ex2f((cf[nt][0] - mx0) * CS);
        float p1 = ex2f((cf[nt][1] - mx0) * CS);
        float p2 = ex2f((cf[nt][2] - mx1) * CS);
        float p3 = ex2f((cf[nt][3] - mx1) * CS);
        cf[nt][0] = p0; cf[nt][1] = p1; cf[nt][2] = p2; cf[nt][3] = p3;
        l0 += p0 + p1; l1 += p2 + p3;
    }
    l0 += __shfl_xor_sync(0xffffffffu, l0, 1);
    l0 += __shfl_xor_sync(0xffffffffu, l0, 2);
    l1 += __shfl_xor_sync(0xffffffffu, l1, 1);
    l1 += __shfl_xor_sync(0xffffffffu, l1, 2);
    const float inv0 = 1.f / l0, inv1 = 1.f / l1;

    // now V must be resident
    CP_WAIT0();
    __syncthreads();

    // ---- O = P V (B-frags via ldmatrix.trans from row-major V) ----
    float of[8][4];
    #pragma unroll
    for (int i = 0; i < 8; i++)
        #pragma unroll
        for (int q = 0; q < 4; q++) of[i][q] = 0.f;

    #pragma unroll
    for (int kt = 0; kt < 8; kt++) {
        uint32_t ah[4];
        ah[0] = packh2(cf[2*kt][0],   cf[2*kt][1]);
        ah[1] = packh2(cf[2*kt][2],   cf[2*kt][3]);
        ah[2] = packh2(cf[2*kt+1][0], cf[2*kt+1][1]);
        ah[3] = packh2(cf[2*kt+1][2], cf[2*kt+1][3]);
        const uint32_t vrow = sb + OFF_V + kt * (16 * QK_STRIDE_B) + v_off;
        #pragma unroll
        for (int np = 0; np < 4; np++) {
            uint32_t vh[4];
            LDSM4T(vh[0], vh[1], vh[2], vh[3], vrow + np * 32);
            MMA_F32(of[2*np],   ah, vh[0], vh[1]);
            MMA_F32(of[2*np+1], ah, vh[2], vh[3]);
        }
    }

    // ---- write A = softmax(S)V as fp16 ----
    const int row  = pb * 128 + wid * 16 + (lane >> 2);
    const int colb = h * 64 + (lane & 3) * 2;
    #pragma unroll
    for (int nt = 0; nt < 8; nt++) {
        size_t off0 = (size_t)row * D_MODEL + colb + nt * 8;
        size_t off1 = off0 + 8 * D_MODEL;
        *reinterpret_cast<uint32_t*>(g_A + off0) = packh2(of[nt][0] * inv0, of[nt][1] * inv0);
        *reinterpret_cast<uint32_t*>(g_A + off1) = packh2(of[nt][2] * inv1, of[nt][3] * inv1);
    }
}

// ---------------------------------------------------------------------------
extern "C" void kernel_launch(void* const* d_in, const int* in_sizes, int n_in,
                              void* d_out, int out_size)
{
    const float* x  = (const float*)d_in[0];
    // d_in[1] = coords (unused by reference)
    const float* Wq = (const float*)d_in[2];
    const float* bq = (const float*)d_in[3];
    const float* Wk = (const float*)d_in[4];
    const float* bk = (const float*)d_in[5];
    const float* Wv = (const float*)d_in[6];
    const float* bv = (const float*)d_in[7];
    const float* Wo = (const float*)d_in[8];
    const float* bo = (const float*)d_in[9];
    float* out = (float*)d_out;

    __half *xh, *Qp, *Kp, *Vp, *Ap, *wp;
    cudaGetSymbolAddress((void**)&xh, g_x);
    cudaGetSymbolAddress((void**)&Qp, g_Q);
    cudaGetSymbolAddress((void**)&Kp, g_K);
    cudaGetSymbolAddress((void**)&Vp, g_V);
    cudaGetSymbolAddress((void**)&Ap, g_A);
    cudaGetSymbolAddress((void**)&wp, g_w);

    cudaFuncSetAttribute(gemm_f16<true>,  cudaFuncAttributeMaxDynamicSharedMemorySize, GEMM_SMEM);
    cudaFuncSetAttribute(gemm_f16<false>, cudaFuncAttributeMaxDynamicSharedMemorySize, GEMM_SMEM);
    cudaFuncSetAttribute(attn_mma_kernel, cudaFuncAttributeMaxDynamicSharedMemorySize, ATTN_SMEM);

    // launch 1: fused prep — transpose/convert weights (z<4) + convert x (z=4)
    dim3 pgrid(32, 32, 5), pblk(32, 8);
    prep_kernel<<<pgrid, pblk>>>(Wq, Wk, Wv, Wo, (const float4*)x, (uint32_t*)xh);

    // launch 2: fused Q/K/V projection (planes 0-2 of g_w), fp16 out
    dim3 qkv_grid(24, M_TOTAL / 128);   // 6144 CTAs (128x128 tiles)
    gemm_f16<false><<<qkv_grid, 256, GEMM_SMEM>>>(xh, wp, bq, bk, bv,
                                                  nullptr, Qp, Kp, Vp);

    // launch 3: tensor-core attention (fp16 A)
    dim3 agrid(NUM_HEADS, NBLK);
    attn_mma_kernel<<<agrid, 256, ATTN_SMEM>>>();

    // launch 4: output projection (plane 3 of g_w), fp32 out
    dim3 o_grid(8, M_TOTAL / 128);
    gemm_f16<true><<<o_grid, 256, GEMM_SMEM>>>(Ap, wp + (size_t)3 * D_MODEL * D_MODEL,
                                               bo, bo, bo, out, nullptr, nullptr, nullptr);
}